// round 4
// baseline (speedup 1.0000x reference)
#include <cuda_runtime.h>
#include <math.h>

#define NPTS   4096
#define NBATCH 16
#define NSAMP  1024
#define NK     32
#define NROWS  (NBATCH*NSAMP*NK)      /* 524288 */
#define OUT_OFF (NBATCH*NSAMP*3)      /* 49152  */

// ---------------- device scratch (no allocations allowed) ----------------
__device__ float  g_centroids[NBATCH*NSAMP*3];
__device__ float  g_x0[(size_t)NROWS*68];
__device__ float  g_y0[(size_t)NROWS*64];
__device__ float  g_y1[(size_t)NROWS*64];
__device__ float  g_y2[(size_t)NROWS*128];
__device__ double g_sums[512];
__device__ float  g_scale[256];
__device__ float  g_shift[256];

__global__ void zero_stats_kernel() {
    int t = threadIdx.x;
    if (t < 512) g_sums[t] = 0.0;
}

// ============================ FPS =========================================
// dist = min(dist, |p-c|^2); far = argmax(dist) (first index on tie).
// Packed key (bits<<32)|(4095-idx): max => largest dist, smallest idx.
// NOTE: verified bit-exact on this dataset (output 0 rel_err == 0) — do not touch.
__global__ __launch_bounds__(1024) void fps_kernel(const float* __restrict__ data,
                                                   const int* __restrict__ initf,
                                                   float* __restrict__ out) {
    const int b = blockIdx.x, tid = threadIdx.x;
    const int lane = tid & 31, wid = tid >> 5;
    __shared__ unsigned long long s_red[32];
    __shared__ int s_far;
    const float* db = data + (size_t)b * NPTS * 3;

    float px[4], py[4], pz[4], dist[4];
#pragma unroll
    for (int i = 0; i < 4; i++) {
        int n = tid + i * 1024;
        px[i] = db[n*3+0]; py[i] = db[n*3+1]; pz[i] = db[n*3+2];
        dist[i] = 1e10f;
    }
    int far = initf[b];

    for (int s = 0; s < NSAMP; s++) {
        float cx = __ldg(db + far*3 + 0);
        float cy = __ldg(db + far*3 + 1);
        float cz = __ldg(db + far*3 + 2);
        if (tid == 0) {
            int o = (b*NSAMP + s) * 3;
            out[o] = cx; out[o+1] = cy; out[o+2] = cz;
            g_centroids[o] = cx; g_centroids[o+1] = cy; g_centroids[o+2] = cz;
        }
        unsigned long long best = 0ull;
#pragma unroll
        for (int i = 0; i < 4; i++) {
            float dx = px[i]-cx, dy = py[i]-cy, dz = pz[i]-cz;
            float d = dx*dx + dy*dy + dz*dz;
            dist[i] = fminf(dist[i], d);
            unsigned long long key =
                ((unsigned long long)__float_as_uint(dist[i]) << 32) |
                (unsigned)(4095 - (tid + i*1024));
            best = best > key ? best : key;
        }
#pragma unroll
        for (int off = 16; off; off >>= 1) {
            unsigned long long o = __shfl_down_sync(0xffffffffu, best, off);
            best = best > o ? best : o;
        }
        if (lane == 0) s_red[wid] = best;
        __syncthreads();
        if (wid == 0) {
            unsigned long long v = s_red[lane];
#pragma unroll
            for (int off = 16; off; off >>= 1) {
                unsigned long long o = __shfl_down_sync(0xffffffffu, v, off);
                v = v > o ? v : o;
            }
            if (lane == 0) s_far = 4095 - (int)(v & 0xFFFFFFFFull);
        }
        __syncthreads();
        far = s_far;
    }
}

// ==================== stage 2+3: top64 -> top32 -> x0 rows ================
struct Stage3 {
    float px[64], py[64], pz[64];
    unsigned long long sk[64];
    float snx[32], sny[32], snz[32], zw[32];
    int   tk[32];
};

__device__ __forceinline__ unsigned ord_f32(float v) {
    unsigned u = __float_as_uint(v);
    return (u & 0x80000000u) ? ~u : (u | 0x80000000u);
}

// Bit-exact replication of the reference square-dist:
//   dot: FMA k-chain (Eigen/cublas accumulation order k=0,1,2)
//   norms: separate mul + left-assoc add (XLA never FMA-contracts across HLOs)
//   combine: ((-2*e) + ||a||^2) + ||b||^2, left-assoc, -2*e exact
__device__ __forceinline__ float sqdist_ref(float cx, float cy, float cz, float an2,
                                            float x, float y, float z) {
    float e   = __fmaf_rn(cz, z, __fmaf_rn(cy, y, __fmul_rn(cx, x)));
    float bn2 = __fadd_rn(__fadd_rn(__fmul_rn(x, x), __fmul_rn(y, y)), __fmul_rn(z, z));
    return __fadd_rn(__fadd_rn(__fmul_rn(-2.f, e), an2), bn2);
}

__global__ __launch_bounds__(256) void build_kernel(const float* __restrict__ data,
                                                    const float* __restrict__ feat) {
    __shared__ __align__(16) unsigned int s_hist[8192];
    __shared__ unsigned long long s_cand[1024];
    __shared__ int s_tot[256];
    __shared__ int s_T, s_m;

    const int tid = threadIdx.x;
    const int b = blockIdx.x >> 10, s = blockIdx.x & 1023;
    const float* db = data + (size_t)b * NPTS * 3;
    const int co = (b*NSAMP + s) * 3;
    const float cx = g_centroids[co], cy = g_centroids[co+1], cz = g_centroids[co+2];
    const float an2 = __fadd_rn(__fadd_rn(__fmul_rn(cx, cx), __fmul_rn(cy, cy)),
                                __fmul_rn(cz, cz));

    for (int i = tid; i < 8192; i += 256) s_hist[i] = 0u;
    if (tid == 0) s_m = 0;
    __syncthreads();

    // pass 1: histogram of ordered-float keys (top 13 bits)
    for (int i = 0; i < 16; i++) {
        int n = tid + i * 256;
        float x = db[n*3], y = db[n*3+1], z = db[n*3+2];
        float v = sqdist_ref(cx, cy, cz, an2, x, y, z);
        atomicAdd(&s_hist[ord_f32(v) >> 19], 1u);
    }
    __syncthreads();

    // suffix counts over 256 chunks of 32 bins
    unsigned tot = 0;
    for (int j = 0; j < 32; j++) tot += s_hist[tid*32 + j];
    s_tot[tid] = (int)tot;
    __syncthreads();
    for (int off = 1; off < 256; off <<= 1) {
        int add = (tid + off < 256) ? s_tot[tid + off] : 0;
        __syncthreads();
        s_tot[tid] += add;
        __syncthreads();
    }
    unsigned cum = (tid < 255) ? (unsigned)s_tot[tid + 1] : 0u;
    for (int j = 31; j >= 0; j--) {
        unsigned h = s_hist[tid*32 + j];
        if (cum < 64u && cum + h >= 64u) s_T = tid*32 + j;   // unique crossing
        cum += h;
    }
    __syncthreads();
    const int T = s_T;

    // pass 2: collect candidates with key-bin >= T
    for (int i = 0; i < 16; i++) {
        int n = tid + i * 256;
        float x = db[n*3], y = db[n*3+1], z = db[n*3+2];
        float v = sqdist_ref(cx, cy, cz, an2, x, y, z);
        unsigned u = ord_f32(v);
        if ((int)(u >> 19) >= T) {
            int slot = atomicAdd(&s_m, 1);
            if (slot < 1024)
                s_cand[slot] = ((unsigned long long)u << 32) | (unsigned)(4095 - n);
        }
    }
    __syncthreads();
    int M = s_m; if (M > 1024) M = 1024;
    int P = 64; while (P < M) P <<= 1;
    for (int i = M + tid; i < P; i += 256) s_cand[i] = 0ull;

    // bitonic sort descending on P candidates
    for (int k = 2; k <= P; k <<= 1)
        for (int j = k >> 1; j > 0; j >>= 1) {
            __syncthreads();
            for (int i = tid; i < P; i += 256) {
                int ix = i ^ j;
                if (ix > i) {
                    unsigned long long a = s_cand[i], c = s_cand[ix];
                    if (((i & k) == 0) ? (a < c) : (a > c)) { s_cand[i] = c; s_cand[ix] = a; }
                }
            }
        }
    __syncthreads();

    // stage 3 scratch aliases the (now-dead) histogram
    Stage3* st = (Stage3*)s_hist;
    if (tid < 64) {
        int id = 4095 - (int)(unsigned)(s_cand[tid] & 0xFFFFFFFFull);
        st->px[tid] = db[id*3]; st->py[tid] = db[id*3+1]; st->pz[tid] = db[id*3+2];
    }
    __syncthreads();
    if (tid < 64) {
        float sc = fabsf(st->pz[tid] - st->pz[(tid + 63) & 63]);   // roll(+1)
        st->sk[tid] = ((unsigned long long)__float_as_uint(sc) << 32) | (unsigned)(63 - tid);
    }
    // bitonic sort descending on the 64 scores
    for (int k = 2; k <= 64; k <<= 1)
        for (int j = k >> 1; j > 0; j >>= 1) {
            __syncthreads();
            if (tid < 64) {
                int i = tid, ix = i ^ j;
                if (ix > i) {
                    unsigned long long a = st->sk[i], c = st->sk[ix];
                    if (((i & k) == 0) ? (a < c) : (a > c)) { st->sk[i] = c; st->sk[ix] = a; }
                }
            }
        }
    __syncthreads();

    if (tid < 32) {
        int j = 63 - (int)(unsigned)(st->sk[tid] & 63ull);   // tki
        float sx = st->px[j] - cx, sy = st->py[j] - cy, sz = st->pz[j] - cz;
        float w = fabsf(st->pz[j] - cz);
        float m = w;
#pragma unroll
        for (int off = 16; off; off >>= 1) m = fmaxf(m, __shfl_xor_sync(0xffffffffu, m, off));
        float e = expf(w - m);
        float su = e;
#pragma unroll
        for (int off = 16; off; off >>= 1) su += __shfl_xor_sync(0xffffffffu, su, off);
        st->snx[tid] = sx; st->sny[tid] = sy; st->snz[tid] = sz;
        st->zw[tid] = e / su;
        st->tk[tid] = j;
    }
    __syncthreads();

    // write x0 rows (67 cols + zero pad), replicating data_feature[b, tki] bug
    size_t R0 = (size_t)(b*NSAMP + s) * NK;
    for (int e = tid; e < NK * 68; e += 256) {
        int k = e / 68, c = e - k * 68;
        float val;
        if (c < 3)        val = (c == 0 ? st->snx[k] : (c == 1 ? st->sny[k] : st->snz[k])) * st->zw[k];
        else if (c < 67)  val = feat[((size_t)b*NPTS + st->tk[k]) * 64 + (c - 3)] * st->zw[k];
        else              val = 0.f;
        g_x0[(R0 + k) * 68 + c] = val;
    }
}

// ============================ fused GEMM + stats ==========================
template<int LAYER>
__global__ __launch_bounds__(256) void gemm_kernel(const float* __restrict__ W,
                                                   const float* __restrict__ bias) {
    constexpr int KIN   = (LAYER == 0) ? 68 : 64;
    constexpr int KREAL = (LAYER == 0) ? 67 : 64;
    constexpr int OUT   = (LAYER == 2) ? 128 : 64;
    constexpr int RG    = (LAYER == 2) ? 16 : 32;   // row groups
    constexpr int RPB   = RG * 8;                   // rows per CTA
    constexpr int XS    = RPB + 4;                  // padded smem stride

    extern __shared__ float sm[];
    float*  s_x   = sm;                  // [KIN][XS] transposed
    float*  s_w   = sm + KIN * XS;       // [KIN][OUT]
    double* s_sum = (double*)(s_w + KIN * OUT);
    double* s_sq  = s_sum + OUT;

    const float* X = (LAYER == 0) ? g_x0 : (LAYER == 1) ? g_y0 : g_y1;
    float*       Y = (LAYER == 0) ? g_y0 : (LAYER == 1) ? g_y1 : g_y2;
    const int scoff = (LAYER == 1) ? 0 : 64;
    double* sums = g_sums + ((LAYER == 0) ? 0 : (LAYER == 1) ? 128 : 256);

    const int tid = threadIdx.x;
    const size_t row0 = (size_t)blockIdx.x * RPB;

    if (tid < OUT) { s_sum[tid] = 0.0; s_sq[tid] = 0.0; }
    for (int i = tid; i < KIN * OUT; i += 256) {
        int k = i / OUT, c = i - k * OUT;
        s_w[k * OUT + c] = (k < KREAL) ? W[c * KREAL + k] : 0.f;
    }
    for (int i = tid; i < RPB * KIN; i += 256) {
        int r = i / KIN, k = i - r * KIN;
        float v = X[(row0 + r) * KIN + k];
        if (LAYER > 0)
            v = fmaxf(fmaf(v, __ldg(&g_scale[scoff + k]), __ldg(&g_shift[scoff + k])), 0.f);
        s_x[k * XS + r] = v;
    }
    __syncthreads();

    const int cg = tid / RG, rg = tid % RG;
    float acc[8][8];
#pragma unroll
    for (int i = 0; i < 8; i++)
#pragma unroll
        for (int j = 0; j < 8; j++) acc[i][j] = 0.f;

#pragma unroll 4
    for (int k = 0; k < KIN; k++) {
        float xv[8], wv[8];
#pragma unroll
        for (int i = 0; i < 8; i++) xv[i] = s_x[k * XS + rg + RG * i];
#pragma unroll
        for (int j = 0; j < 8; j++) wv[j] = s_w[k * OUT + cg * 8 + j];
#pragma unroll
        for (int i = 0; i < 8; i++)
#pragma unroll
            for (int j = 0; j < 8; j++) acc[i][j] = fmaf(xv[i], wv[j], acc[i][j]);
    }

    float bl[8];
#pragma unroll
    for (int j = 0; j < 8; j++) bl[j] = bias[cg * 8 + j];
    float psum[8], psq[8];
#pragma unroll
    for (int j = 0; j < 8; j++) { psum[j] = 0.f; psq[j] = 0.f; }

#pragma unroll
    for (int i = 0; i < 8; i++) {
        size_t row = row0 + rg + RG * i;
        float yv[8];
#pragma unroll
        for (int j = 0; j < 8; j++) {
            yv[j] = acc[i][j] + bl[j];
            psum[j] += yv[j];
            psq[j]  = fmaf(yv[j], yv[j], psq[j]);
        }
        float4* dst = (float4*)&Y[row * OUT + cg * 8];
        dst[0] = make_float4(yv[0], yv[1], yv[2], yv[3]);
        dst[1] = make_float4(yv[4], yv[5], yv[6], yv[7]);
    }
#pragma unroll
    for (int j = 0; j < 8; j++) {
        for (int off = RG / 2; off; off >>= 1) {
            psum[j] += __shfl_down_sync(0xffffffffu, psum[j], off, RG);
            psq[j]  += __shfl_down_sync(0xffffffffu, psq[j],  off, RG);
        }
    }
    if (rg == 0) {
#pragma unroll
        for (int j = 0; j < 8; j++) {
            atomicAdd(&s_sum[cg * 8 + j], (double)psum[j]);
            atomicAdd(&s_sq[cg * 8 + j],  (double)psq[j]);
        }
    }
    __syncthreads();
    if (tid < OUT) {
        atomicAdd(&sums[tid],       s_sum[tid]);
        atomicAdd(&sums[OUT + tid], s_sq[tid]);
    }
}

__global__ void finalize_kernel(const float* __restrict__ g, const float* __restrict__ be,
                                int O, int soff, int scoff) {
    int c = threadIdx.x;
    if (c >= O) return;
    double n = (double)NROWS;
    double mean = g_sums[soff + c] / n;
    double var  = g_sums[soff + O + c] / n - mean * mean;
    double sc   = (double)g[c] * rsqrt(var + 1e-5);
    g_scale[scoff + c] = (float)sc;
    g_shift[scoff + c] = (float)((double)be[c] - mean * sc);
}

__global__ __launch_bounds__(128) void maxpool_kernel(float* __restrict__ out) {
    int bs = blockIdx.x;      // 16384
    int c  = threadIdx.x;     // 128
    float sc = g_scale[128 + c], sh = g_shift[128 + c];
    float m = -1e30f;
    size_t base = (size_t)bs * NK * 128 + c;
    for (int k = 0; k < NK; k++) {
        float v = g_y2[base + (size_t)k * 128];
        v = fmaxf(fmaf(v, sc, sh), 0.f);
        m = fmaxf(m, v);
    }
    out[OUT_OFF + (size_t)bs * 128 + c] = m;
}

// ============================ launcher ====================================
extern "C" void kernel_launch(void* const* d_in, const int* in_sizes, int n_in,
                              void* d_out, int out_size) {
    const float* data = (const float*)d_in[0];
    const float* feat = (const float*)d_in[1];
    const int*   initf = (const int*)d_in[2];
    const float* W0 = (const float*)d_in[3];  const float* b0 = (const float*)d_in[4];
    const float* g0 = (const float*)d_in[5];  const float* be0 = (const float*)d_in[6];
    const float* W1 = (const float*)d_in[7];  const float* b1 = (const float*)d_in[8];
    const float* g1 = (const float*)d_in[9];  const float* be1 = (const float*)d_in[10];
    const float* W2 = (const float*)d_in[11]; const float* b2 = (const float*)d_in[12];
    const float* g2 = (const float*)d_in[13]; const float* be2 = (const float*)d_in[14];
    float* out = (float*)d_out;

    const int sm0 = (68*260 + 68*64) * 4 + 64*16;    // 89152
    const int sm1 = (64*260 + 64*64) * 4 + 64*16;    // 83968
    const int sm2 = (64*132 + 64*128) * 4 + 128*16;  // 68608
    cudaFuncSetAttribute((const void*)gemm_kernel<0>, cudaFuncAttributeMaxDynamicSharedMemorySize, sm0);
    cudaFuncSetAttribute((const void*)gemm_kernel<1>, cudaFuncAttributeMaxDynamicSharedMemorySize, sm1);
    cudaFuncSetAttribute((const void*)gemm_kernel<2>, cudaFuncAttributeMaxDynamicSharedMemorySize, sm2);

    zero_stats_kernel<<<1, 512>>>();
    fps_kernel<<<NBATCH, 1024>>>(data, initf, out);
    build_kernel<<<NBATCH * NSAMP, 256>>>(data, feat);
    gemm_kernel<0><<<NROWS / 256, 256, sm0>>>(W0, b0);
    finalize_kernel<<<1, 128>>>(g0, be0, 64, 0, 0);
    gemm_kernel<1><<<NROWS / 256, 256, sm1>>>(W1, b1);
    finalize_kernel<<<1, 128>>>(g1, be1, 64, 128, 64);
    gemm_kernel<2><<<NROWS / 128, 256, sm2>>>(W2, b2);
    finalize_kernel<<<1, 128>>>(g2, be2, 128, 256, 128);
    maxpool_kernel<<<NBATCH * NSAMP, 128>>>(out);
}

// round 5
// speedup vs baseline: 1.0955x; 1.0955x over previous
#include <cuda_runtime.h>
#include <math.h>

#define NPTS   4096
#define NBATCH 16
#define NSAMP  1024
#define NK     32
#define NROWS  (NBATCH*NSAMP*NK)      /* 524288 */
#define NSAMPT (NBATCH*NSAMP)         /* 16384  */
#define OUT_OFF (NBATCH*NSAMP*3)      /* 49152  */

// ---------------- device scratch (no allocations allowed) ----------------
__device__ float  g_centroids[NBATCH*NSAMP*3];
__device__ float  g_x0[(size_t)NROWS*68];
__device__ float  g_y0[(size_t)NROWS*64];
__device__ float  g_y1[(size_t)NROWS*64];
__device__ float  g_ymax[(size_t)NSAMPT*128];
__device__ float  g_ymin[(size_t)NSAMPT*128];
__device__ double g_sums[512];
__device__ float  g_scale[256];
__device__ float  g_shift[256];

__global__ void zero_stats_kernel() {
    int t = threadIdx.x;
    if (t < 512) g_sums[t] = 0.0;
}

// ---------------- packed f32x2 helpers (exact RN f32 math, 2x issue) -----
__device__ __forceinline__ unsigned long long pk_dup(float x) {
    unsigned long long r; unsigned u = __float_as_uint(x);
    asm("mov.b64 %0, {%1, %1};" : "=l"(r) : "r"(u));
    return r;
}
__device__ __forceinline__ void fma2(unsigned long long& d, unsigned long long a,
                                     unsigned long long b) {
    asm("fma.rn.f32x2 %0, %1, %2, %0;" : "+l"(d) : "l"(a), "l"(b));
}
__device__ __forceinline__ void unpk(unsigned long long v, float& lo, float& hi) {
    unsigned a, b;
    asm("mov.b64 {%0, %1}, %2;" : "=r"(a), "=r"(b) : "l"(v));
    lo = __uint_as_float(a); hi = __uint_as_float(b);
}

// ============================ FPS =========================================
// dist = min(dist, |p-c|^2); far = argmax (first index on tie).
// Centroid broadcast via smem owner-publish; all warps redundantly reduce
// the 32 warp-maxima so everyone knows `far` with 2 syncs/iter.
// Float update lines verbatim from the bit-exact round-3 version.
__global__ __launch_bounds__(1024) void fps_kernel(const float* __restrict__ data,
                                                   const int* __restrict__ initf,
                                                   float* __restrict__ out) {
    const int b = blockIdx.x, tid = threadIdx.x;
    const int lane = tid & 31, wid = tid >> 5;
    __shared__ unsigned long long s_red[32];
    __shared__ float s_c[3];
    const float* db = data + (size_t)b * NPTS * 3;

    float px[4], py[4], pz[4], dist[4];
#pragma unroll
    for (int i = 0; i < 4; i++) {
        int n = tid + i * 1024;
        px[i] = db[n*3+0]; py[i] = db[n*3+1]; pz[i] = db[n*3+2];
        dist[i] = 1e10f;
    }
    int far = initf[b];

    for (int s = 0; s < NSAMP; s++) {
        if ((far & 1023) == tid) {
            int i = far >> 10;
            float ox = (i == 0) ? px[0] : (i == 1) ? px[1] : (i == 2) ? px[2] : px[3];
            float oy = (i == 0) ? py[0] : (i == 1) ? py[1] : (i == 2) ? py[2] : py[3];
            float oz = (i == 0) ? pz[0] : (i == 1) ? pz[1] : (i == 2) ? pz[2] : pz[3];
            s_c[0] = ox; s_c[1] = oy; s_c[2] = oz;
            int o = (b*NSAMP + s) * 3;
            out[o] = ox; out[o+1] = oy; out[o+2] = oz;
            g_centroids[o] = ox; g_centroids[o+1] = oy; g_centroids[o+2] = oz;
        }
        __syncthreads();
        float cx = s_c[0], cy = s_c[1], cz = s_c[2];
        unsigned long long best = 0ull;
#pragma unroll
        for (int i = 0; i < 4; i++) {
            float dx = px[i]-cx, dy = py[i]-cy, dz = pz[i]-cz;
            float d = dx*dx + dy*dy + dz*dz;
            dist[i] = fminf(dist[i], d);
            unsigned long long key =
                ((unsigned long long)__float_as_uint(dist[i]) << 32) |
                (unsigned)(4095 - (tid + i*1024));
            best = best > key ? best : key;
        }
#pragma unroll
        for (int off = 16; off; off >>= 1) {
            unsigned long long o = __shfl_xor_sync(0xffffffffu, best, off);
            best = best > o ? best : o;
        }
        if (lane == 0) s_red[wid] = best;
        __syncthreads();
        unsigned long long v = s_red[lane];
#pragma unroll
        for (int off = 16; off; off >>= 1) {
            unsigned long long o = __shfl_xor_sync(0xffffffffu, v, off);
            v = v > o ? v : o;
        }
        far = 4095 - (int)(v & 0xFFFFFFFFull);
    }
}

// ==================== stage 2+3: top64 -> top32 -> x0 rows ================
struct Stage3 {
    float px[64], py[64], pz[64];
    unsigned long long sk[64];
    float snx[32], sny[32], snz[32], zw[32];
    int   tk[32];
};

__device__ __forceinline__ unsigned ord_f32(float v) {
    unsigned u = __float_as_uint(v);
    return (u & 0x80000000u) ? ~u : (u | 0x80000000u);
}

// Bit-exact replication of the reference square-dist (verified round 4 pass):
__device__ __forceinline__ float sqdist_ref(float cx, float cy, float cz, float an2,
                                            float x, float y, float z) {
    float e   = __fmaf_rn(cz, z, __fmaf_rn(cy, y, __fmul_rn(cx, x)));
    float bn2 = __fadd_rn(__fadd_rn(__fmul_rn(x, x), __fmul_rn(y, y)), __fmul_rn(z, z));
    return __fadd_rn(__fadd_rn(__fmul_rn(-2.f, e), an2), bn2);
}

__global__ __launch_bounds__(256) void build_kernel(const float* __restrict__ data,
                                                    const float* __restrict__ feat) {
    extern __shared__ char bsm[];
    unsigned long long* s_keys = (unsigned long long*)bsm;            // 4096 * 8
    unsigned int*       s_hist = (unsigned int*)(bsm + 32768);        // 4096 * 4
    unsigned long long* s_cand = (unsigned long long*)(bsm + 49152);  // 1024 * 8
    int*                s_tot  = (int*)(bsm + 57344);                 // 256 * 4
    int*                s_ctl  = (int*)(bsm + 58368);                 // [0]=T [1]=m

    const int tid = threadIdx.x;
    const int b = blockIdx.x >> 10, s = blockIdx.x & 1023;
    const float* db = data + (size_t)b * NPTS * 3;
    const int co = (b*NSAMP + s) * 3;
    const float cx = g_centroids[co], cy = g_centroids[co+1], cz = g_centroids[co+2];
    const float an2 = __fadd_rn(__fadd_rn(__fmul_rn(cx, cx), __fmul_rn(cy, cy)),
                                __fmul_rn(cz, cz));

    for (int i = tid; i < 4096; i += 256) s_hist[i] = 0u;
    if (tid == 0) s_ctl[1] = 0;
    __syncthreads();

    // pass 1: compute keys once, cache in smem, histogram top 12 bits
    for (int i = 0; i < 16; i++) {
        int n = tid + i * 256;
        float x = db[n*3], y = db[n*3+1], z = db[n*3+2];
        float v = sqdist_ref(cx, cy, cz, an2, x, y, z);
        unsigned u = ord_f32(v);
        s_keys[n] = ((unsigned long long)u << 32) | (unsigned)(4095 - n);
        atomicAdd(&s_hist[u >> 20], 1u);
    }
    __syncthreads();

    // suffix counts over 256 chunks of 16 bins
    unsigned tot = 0;
    for (int j = 0; j < 16; j++) tot += s_hist[tid*16 + j];
    s_tot[tid] = (int)tot;
    __syncthreads();
    for (int off = 1; off < 256; off <<= 1) {
        int add = (tid + off < 256) ? s_tot[tid + off] : 0;
        __syncthreads();
        s_tot[tid] += add;
        __syncthreads();
    }
    unsigned cum = (tid < 255) ? (unsigned)s_tot[tid + 1] : 0u;
    for (int j = 15; j >= 0; j--) {
        unsigned h = s_hist[tid*16 + j];
        if (cum < 64u && cum + h >= 64u) s_ctl[0] = tid*16 + j;   // unique crossing
        cum += h;
    }
    __syncthreads();
    const unsigned T = (unsigned)s_ctl[0];

    // pass 2: pure smem scan, push candidates with bin >= T
    for (int i = 0; i < 16; i++) {
        int n = tid + i * 256;
        unsigned long long key = s_keys[n];
        if ((unsigned)(key >> 52) >= T) {
            int slot = atomicAdd(&s_ctl[1], 1);
            if (slot < 1024) s_cand[slot] = key;
        }
    }
    __syncthreads();
    int M = s_ctl[1]; if (M > 1024) M = 1024;
    int P = 64; while (P < M) P <<= 1;
    for (int i = M + tid; i < P; i += 256) s_cand[i] = 0ull;

    // bitonic sort descending
    for (int k = 2; k <= P; k <<= 1)
        for (int j = k >> 1; j > 0; j >>= 1) {
            __syncthreads();
            for (int i = tid; i < P; i += 256) {
                int ix = i ^ j;
                if (ix > i) {
                    unsigned long long a = s_cand[i], c = s_cand[ix];
                    if (((i & k) == 0) ? (a < c) : (a > c)) { s_cand[i] = c; s_cand[ix] = a; }
                }
            }
        }
    __syncthreads();

    Stage3* st = (Stage3*)s_hist;   // alias dead histogram
    if (tid < 64) {
        int id = 4095 - (int)(unsigned)(s_cand[tid] & 0xFFFFFFFFull);
        st->px[tid] = db[id*3]; st->py[tid] = db[id*3+1]; st->pz[tid] = db[id*3+2];
    }
    __syncthreads();
    if (tid < 64) {
        float sc = fabsf(st->pz[tid] - st->pz[(tid + 63) & 63]);   // roll(+1)
        st->sk[tid] = ((unsigned long long)__float_as_uint(sc) << 32) | (unsigned)(63 - tid);
    }
    for (int k = 2; k <= 64; k <<= 1)
        for (int j = k >> 1; j > 0; j >>= 1) {
            __syncthreads();
            if (tid < 64) {
                int i = tid, ix = i ^ j;
                if (ix > i) {
                    unsigned long long a = st->sk[i], c = st->sk[ix];
                    if (((i & k) == 0) ? (a < c) : (a > c)) { st->sk[i] = c; st->sk[ix] = a; }
                }
            }
        }
    __syncthreads();

    if (tid < 32) {
        int j = 63 - (int)(unsigned)(st->sk[tid] & 63ull);   // tki
        float sx = st->px[j] - cx, sy = st->py[j] - cy, sz = st->pz[j] - cz;
        float w = fabsf(st->pz[j] - cz);
        float m = w;
#pragma unroll
        for (int off = 16; off; off >>= 1) m = fmaxf(m, __shfl_xor_sync(0xffffffffu, m, off));
        float e = expf(w - m);
        float su = e;
#pragma unroll
        for (int off = 16; off; off >>= 1) su += __shfl_xor_sync(0xffffffffu, su, off);
        st->snx[tid] = sx; st->sny[tid] = sy; st->snz[tid] = sz;
        st->zw[tid] = e / su;
        st->tk[tid] = j;
    }
    __syncthreads();

    size_t R0 = (size_t)(b*NSAMP + s) * NK;
    for (int e = tid; e < NK * 68; e += 256) {
        int k = e / 68, c = e - k * 68;
        float val;
        if (c < 3)        val = (c == 0 ? st->snx[k] : (c == 1 ? st->sny[k] : st->snz[k])) * st->zw[k];
        else if (c < 67)  val = feat[((size_t)b*NPTS + st->tk[k]) * 64 + (c - 3)] * st->zw[k];
        else              val = 0.f;
        g_x0[(R0 + k) * 68 + c] = val;
    }
}

// ==================== GEMM layers 0/1 (f32x2, fused stats) ================
template<int LAYER>
__global__ __launch_bounds__(256) void gemm01_kernel(const float* __restrict__ W,
                                                     const float* __restrict__ bias) {
    constexpr int KIN   = (LAYER == 0) ? 68 : 64;
    constexpr int KREAL = (LAYER == 0) ? 67 : 64;
    constexpr int OUT   = 64;
    constexpr int RPB   = 128;
    constexpr int XS    = RPB + 4;

    extern __shared__ float sm[];
    float* s_x = sm;                 // [KIN][XS]
    float* s_w = sm + KIN * XS;      // [KIN][OUT]

    const float* X = (LAYER == 0) ? g_x0 : g_y0;
    float*       Y = (LAYER == 0) ? g_y0 : g_y1;
    double* sums = g_sums + ((LAYER == 0) ? 0 : 128);

    const int tid = threadIdx.x;
    const int cg = tid >> 5, rg = tid & 31;    // 8 col-groups x 8 cols, 32 row-groups x 4 rows
    const size_t row0 = (size_t)blockIdx.x * RPB;

    for (int i = tid; i < KIN * OUT; i += 256) {
        int k = i / OUT, c = i - k * OUT;
        s_w[k * OUT + c] = (k < KREAL) ? W[c * KREAL + k] : 0.f;
    }
    for (int i = tid; i < RPB * KIN; i += 256) {
        int r = i / KIN, k = i - r * KIN;
        float v = X[(row0 + r) * KIN + k];
        if (LAYER > 0)
            v = fmaxf(fmaf(v, __ldg(&g_scale[k]), __ldg(&g_shift[k])), 0.f);
        s_x[k * XS + r] = v;
    }
    __syncthreads();

    unsigned long long acc[4][4];
#pragma unroll
    for (int i = 0; i < 4; i++)
#pragma unroll
        for (int j = 0; j < 4; j++) acc[i][j] = 0ull;

    const unsigned long long* s_w2 = (const unsigned long long*)s_w;
#pragma unroll 4
    for (int k = 0; k < KIN; k++) {
        float4 xq = *(const float4*)(s_x + k * XS + 4 * rg);
        unsigned long long a0 = pk_dup(xq.x), a1 = pk_dup(xq.y),
                           a2 = pk_dup(xq.z), a3 = pk_dup(xq.w);
        ulonglong2 b01 = *(const ulonglong2*)(s_w2 + ((k * OUT + cg * 8) >> 1));
        ulonglong2 b23 = *(const ulonglong2*)(s_w2 + ((k * OUT + cg * 8) >> 1) + 2);
        fma2(acc[0][0], a0, b01.x); fma2(acc[0][1], a0, b01.y);
        fma2(acc[0][2], a0, b23.x); fma2(acc[0][3], a0, b23.y);
        fma2(acc[1][0], a1, b01.x); fma2(acc[1][1], a1, b01.y);
        fma2(acc[1][2], a1, b23.x); fma2(acc[1][3], a1, b23.y);
        fma2(acc[2][0], a2, b01.x); fma2(acc[2][1], a2, b01.y);
        fma2(acc[2][2], a2, b23.x); fma2(acc[2][3], a2, b23.y);
        fma2(acc[3][0], a3, b01.x); fma2(acc[3][1], a3, b01.y);
        fma2(acc[3][2], a3, b23.x); fma2(acc[3][3], a3, b23.y);
    }

    float bl[8];
#pragma unroll
    for (int j = 0; j < 8; j++) bl[j] = bias[cg * 8 + j];
    float psum[8], psq[8];
#pragma unroll
    for (int j = 0; j < 8; j++) { psum[j] = 0.f; psq[j] = 0.f; }

#pragma unroll
    for (int r = 0; r < 4; r++) {
        float yv[8];
#pragma unroll
        for (int jp = 0; jp < 4; jp++) unpk(acc[r][jp], yv[2*jp], yv[2*jp+1]);
#pragma unroll
        for (int j = 0; j < 8; j++) {
            yv[j] = yv[j] + bl[j];
            psum[j] += yv[j];
            psq[j]  = fmaf(yv[j], yv[j], psq[j]);
        }
        size_t row = row0 + 4 * rg + r;
        float4* dst = (float4*)&Y[row * OUT + cg * 8];
        dst[0] = make_float4(yv[0], yv[1], yv[2], yv[3]);
        dst[1] = make_float4(yv[4], yv[5], yv[6], yv[7]);
    }
#pragma unroll
    for (int j = 0; j < 8; j++) {
#pragma unroll
        for (int off = 16; off; off >>= 1) {
            psum[j] += __shfl_down_sync(0xffffffffu, psum[j], off);
            psq[j]  += __shfl_down_sync(0xffffffffu, psq[j],  off);
        }
    }
    if (rg == 0) {
#pragma unroll
        for (int j = 0; j < 8; j++) {
            atomicAdd(&sums[cg * 8 + j],       (double)psum[j]);
            atomicAdd(&sums[OUT + cg * 8 + j], (double)psq[j]);
        }
    }
}

// ==================== GEMM layer 2 (f32x2, stats + max/min, no Y) =========
__global__ __launch_bounds__(256) void gemm2_kernel(const float* __restrict__ W,
                                                    const float* __restrict__ bias) {
    constexpr int KIN = 64, OUT = 128, RPB = 64, XS = RPB + 4;

    extern __shared__ float sm[];
    float* s_x = sm;                 // [64][68]
    float* s_w = sm + KIN * XS;      // [64][128]
    double* sums = g_sums + 256;

    const int tid = threadIdx.x;
    const int cg = tid >> 4, rg = tid & 15;    // 16 col-groups x 8 cols, 16 row-groups x 4 rows
    const size_t row0 = (size_t)blockIdx.x * RPB;

    for (int i = tid; i < KIN * OUT; i += 256) {
        int k = i / OUT, c = i - k * OUT;
        s_w[k * OUT + c] = W[c * KIN + k];
    }
    for (int i = tid; i < RPB * KIN; i += 256) {
        int r = i / KIN, k = i - r * KIN;
        float v = g_y1[(row0 + r) * KIN + k];
        v = fmaxf(fmaf(v, __ldg(&g_scale[64 + k]), __ldg(&g_shift[64 + k])), 0.f);
        s_x[k * XS + r] = v;
    }
    __syncthreads();

    unsigned long long acc[4][4];
#pragma unroll
    for (int i = 0; i < 4; i++)
#pragma unroll
        for (int j = 0; j < 4; j++) acc[i][j] = 0ull;

    const unsigned long long* s_w2 = (const unsigned long long*)s_w;
#pragma unroll 4
    for (int k = 0; k < KIN; k++) {
        float4 xq = *(const float4*)(s_x + k * XS + 4 * rg);
        unsigned long long a0 = pk_dup(xq.x), a1 = pk_dup(xq.y),
                           a2 = pk_dup(xq.z), a3 = pk_dup(xq.w);
        ulonglong2 b01 = *(const ulonglong2*)(s_w2 + ((k * OUT + cg * 8) >> 1));
        ulonglong2 b23 = *(const ulonglong2*)(s_w2 + ((k * OUT + cg * 8) >> 1) + 2);
        fma2(acc[0][0], a0, b01.x); fma2(acc[0][1], a0, b01.y);
        fma2(acc[0][2], a0, b23.x); fma2(acc[0][3], a0, b23.y);
        fma2(acc[1][0], a1, b01.x); fma2(acc[1][1], a1, b01.y);
        fma2(acc[1][2], a1, b23.x); fma2(acc[1][3], a1, b23.y);
        fma2(acc[2][0], a2, b01.x); fma2(acc[2][1], a2, b01.y);
        fma2(acc[2][2], a2, b23.x); fma2(acc[2][3], a2, b23.y);
        fma2(acc[3][0], a3, b01.x); fma2(acc[3][1], a3, b01.y);
        fma2(acc[3][2], a3, b23.x); fma2(acc[3][3], a3, b23.y);
    }

    float bl[8];
#pragma unroll
    for (int j = 0; j < 8; j++) bl[j] = bias[cg * 8 + j];
    float psum[8], psq[8], tmax[8], tmin[8];
#pragma unroll
    for (int j = 0; j < 8; j++) {
        psum[j] = 0.f; psq[j] = 0.f; tmax[j] = -1e30f; tmin[j] = 1e30f;
    }

#pragma unroll
    for (int r = 0; r < 4; r++) {
        float yv[8];
#pragma unroll
        for (int jp = 0; jp < 4; jp++) unpk(acc[r][jp], yv[2*jp], yv[2*jp+1]);
#pragma unroll
        for (int j = 0; j < 8; j++) {
            yv[j] = yv[j] + bl[j];
            psum[j] += yv[j];
            psq[j]  = fmaf(yv[j], yv[j], psq[j]);
            tmax[j] = fmaxf(tmax[j], yv[j]);
            tmin[j] = fminf(tmin[j], yv[j]);
        }
    }
    // stats reduce over the 16 threads sharing this col-group (width-16)
#pragma unroll
    for (int j = 0; j < 8; j++) {
#pragma unroll
        for (int off = 8; off; off >>= 1) {
            psum[j] += __shfl_down_sync(0xffffffffu, psum[j], off, 16);
            psq[j]  += __shfl_down_sync(0xffffffffu, psq[j],  off, 16);
        }
    }
    if (rg == 0) {
#pragma unroll
        for (int j = 0; j < 8; j++) {
            atomicAdd(&sums[cg * 8 + j],       (double)psum[j]);
            atomicAdd(&sums[OUT + cg * 8 + j], (double)psq[j]);
        }
    }
    // max/min reduce over the 8 threads of each 32-row sample group (width-8)
#pragma unroll
    for (int j = 0; j < 8; j++) {
#pragma unroll
        for (int off = 4; off; off >>= 1) {
            tmax[j] = fmaxf(tmax[j], __shfl_down_sync(0xffffffffu, tmax[j], off, 8));
            tmin[j] = fminf(tmin[j], __shfl_down_sync(0xffffffffu, tmin[j], off, 8));
        }
    }
    if ((rg & 7) == 0) {
        size_t samp = row0 / 32 + (rg >> 3);
        float* pma = &g_ymax[samp * 128 + cg * 8];
        float* pmi = &g_ymin[samp * 128 + cg * 8];
        ((float4*)pma)[0] = make_float4(tmax[0], tmax[1], tmax[2], tmax[3]);
        ((float4*)pma)[1] = make_float4(tmax[4], tmax[5], tmax[6], tmax[7]);
        ((float4*)pmi)[0] = make_float4(tmin[0], tmin[1], tmin[2], tmin[3]);
        ((float4*)pmi)[1] = make_float4(tmin[4], tmin[5], tmin[6], tmin[7]);
    }
}

__global__ void finalize_kernel(const float* __restrict__ g, const float* __restrict__ be,
                                int O, int soff, int scoff) {
    int c = threadIdx.x;
    if (c >= O) return;
    double n = (double)NROWS;
    double mean = g_sums[soff + c] / n;
    double var  = g_sums[soff + O + c] / n - mean * mean;
    double sc   = (double)g[c] * rsqrt(var + 1e-5);
    g_scale[scoff + c] = (float)sc;
    g_shift[scoff + c] = (float)((double)be[c] - mean * sc);
}

// maxpool via pre-reduced max/min: relu(fma(y,sc,sh)) is monotone in y for
// fixed sign(sc), so max_k relu(sc*y_k+sh) = relu(sc*(sc>=0?max:min)+sh) exactly.
__global__ __launch_bounds__(128) void maxpool_kernel(float* __restrict__ out) {
    int bs = blockIdx.x, c = threadIdx.x;
    float sc = g_scale[128 + c], sh = g_shift[128 + c];
    float v = (sc >= 0.f) ? g_ymax[(size_t)bs * 128 + c] : g_ymin[(size_t)bs * 128 + c];
    out[OUT_OFF + (size_t)bs * 128 + c] = fmaxf(fmaf(v, sc, sh), 0.f);
}

// ============================ launcher ====================================
extern "C" void kernel_launch(void* const* d_in, const int* in_sizes, int n_in,
                              void* d_out, int out_size) {
    const float* data = (const float*)d_in[0];
    const float* feat = (const float*)d_in[1];
    const int*   initf = (const int*)d_in[2];
    const float* W0 = (const float*)d_in[3];  const float* b0 = (const float*)d_in[4];
    const float* g0 = (const float*)d_in[5];  const float* be0 = (const float*)d_in[6];
    const float* W1 = (const float*)d_in[7];  const float* b1 = (const float*)d_in[8];
    const float* g1 = (const float*)d_in[9];  const float* be1 = (const float*)d_in[10];
    const float* W2 = (const float*)d_in[11]; const float* b2 = (const float*)d_in[12];
    const float* g2 = (const float*)d_in[13]; const float* be2 = (const float*)d_in[14];
    float* out = (float*)d_out;

    const int smb = 58368 + 32;                      // build kernel
    const int sm0 = (68*132 + 68*64) * 4;            // 53312
    const int sm1 = (64*132 + 64*64) * 4;            // 50176
    const int sm2 = (64*68 + 64*128) * 4;            // 50176
    cudaFuncSetAttribute((const void*)build_kernel,     cudaFuncAttributeMaxDynamicSharedMemorySize, smb);
    cudaFuncSetAttribute((const void*)gemm01_kernel<0>, cudaFuncAttributeMaxDynamicSharedMemorySize, sm0);
    cudaFuncSetAttribute((const void*)gemm01_kernel<1>, cudaFuncAttributeMaxDynamicSharedMemorySize, sm1);
    cudaFuncSetAttribute((const void*)gemm2_kernel,     cudaFuncAttributeMaxDynamicSharedMemorySize, sm2);

    zero_stats_kernel<<<1, 512>>>();
    fps_kernel<<<NBATCH, 1024>>>(data, initf, out);
    build_kernel<<<NBATCH * NSAMP, 256, smb>>>(data, feat);
    gemm01_kernel<0><<<NROWS / 128, 256, sm0>>>(W0, b0);
    finalize_kernel<<<1, 128>>>(g0, be0, 64, 0, 0);
    gemm01_kernel<1><<<NROWS / 128, 256, sm1>>>(W1, b1);
    finalize_kernel<<<1, 128>>>(g1, be1, 64, 128, 64);
    gemm2_kernel<<<NROWS / 64, 256, sm2>>>(W2, b2);
    finalize_kernel<<<1, 128>>>(g2, be2, 128, 256, 128);
    maxpool_kernel<<<NBATCH * NSAMP, 128>>>(out);
}